// round 7
// baseline (speedup 1.0000x reference)
#include <cuda_runtime.h>

#define HH    128
#define NPIX  16384
#define TPB   256
#define BIMG  2048

// Weight-independent theta table (atan2(y-cy, x-cx)), rebuilt every launch
// (deterministic), read by all 2048 blocks out of L2.
__device__ float g_theta[NPIX];

__global__ void theta_init_kernel() {
    int p = blockIdx.x * blockDim.x + threadIdx.x;
    if (p < NPIX) {
        float fx = (float)(p >> 7) - 64.0f;   // xx - cx
        float fy = (float)(p & 127) - 64.0f;  // yy - cy
        g_theta[p] = atan2f(fy, fx);          // arctan2(yy-cy, xx-cx)
    }
}

__global__ void __launch_bounds__(TPB) decode_kernel(
    const float* __restrict__ W,
    const float* __restrict__ ng,
    const float* __restrict__ nu,
    float* __restrict__ out)
{
    extern __shared__ float s_img[];  // 16384 floats = 64 KB (dynamic)

    __shared__ float4 xtA[HH];   // {A_x, gX, lX, dx2}
    __shared__ float4 xtB[HH];   // {0.5*sin(ax), 0.5*cos(ax), mXf, cpxf}
    __shared__ float4 ytA[HH];   // permuted: {A_y, gY, lY, 0.3*cpy}
    __shared__ float2 ytB[HH];   // permuted: {sin(by), cos(by)}
    __shared__ float  s_w[16];
    __shared__ float  s_mn[8], s_mx[8];

    const int tid = threadIdx.x;
    const int b   = blockIdx.x;

    if (tid < 16) s_w[tid] = W[b * 16 + tid];
    __syncthreads();

    const float w0 = s_w[0],  w1 = s_w[1],  w2 = s_w[2],  w3 = s_w[3];
    const float w4 = s_w[4],  w5 = s_w[5],  w6 = s_w[6],  w7 = s_w[7];
    const float w8 = s_w[8],  w9 = s_w[9],  w10 = s_w[10], w11 = s_w[11];
    const float w12 = s_w[12], w13 = s_w[13], w14 = s_w[14], w15 = s_w[15];

    const float PI = 3.14159265358979323846f;

    // Per-image scalar precomputes (match reference rounding where predicates depend on it)
    const float w06   = w0 * 6.0f;
    const float half  = floorf(fminf(fmaxf(fabsf(w1) * 8.0f + 2.0f, 2.0f), 12.0f));
    const float sqlo  = 64.0f - half, sqhi = 64.0f + half;
    const float off   = truncf(w7 * 5.0f);
    const float bxy   = 64.0f + off;
    const float sig   = 4.0f + fabsf(w7) * 5.0f;
    const float ek    = -0.5f / (sig * sig);
    const float w8_10 = w8 * 10.0f;
    const float cb    = floorf(fminf(fmaxf(fabsf(w9) * 8.0f + 2.0f, 2.0f), 16.0f));
    const int   icb   = (int)cb;
    const float angle = w10 * PI;
    const float ca    = cosf(angle);   // accurate: predicate-critical
    const float sa    = sinf(angle);
    const float m11   = w11 * 4.0f;
    const float c12   = 0.2f * w12;
    const float c13   = 0.2f * w13;
    const float c14   = 1.0f + w14;
    const bool  inv15 = (w15 > 0.0f);

    // ---- Build per-x / per-y tables ----
    if (tid < HH) {
        const int i = tid;
        const float fi = (float)i;
        const float di = fi - 64.0f;
        float Ax  = 0.5f * sinf(w2 * 2.0f * PI * fi * (1.0f / 128.0f));
        float gX  = expf(ek * (fi - bxy) * (fi - bxy));
        float lX  = ca * di;
        float dx2 = di * di;
        float sax, cax;
        sincosf(w4 * PI * fi * (1.0f / 256.0f), &sax, &cax);
        float mXf  = (fi >= sqlo && fi < sqhi) ? 1.0f : 0.0f;
        float cpxf = (float)((i / icb) & 1);
        xtA[i] = make_float4(Ax, gX, lX, dx2);
        xtB[i] = make_float4(0.5f * sax, 0.5f * cax, mXf, cpxf);
    } else {
        const int y = tid - HH;
        const float fy = (float)y;
        const float dy = fy - 64.0f;
        float Ay = 0.5f * sinf(w3 * 2.0f * PI * fy * (1.0f / 128.0f))
                 + 0.5f * sinf((fy + w5 * 10.0f) * PI * (1.0f / 128.0f));
        float gY = expf(ek * (fy - bxy) * (fy - bxy));
        float lY = sa * dy;
        float ty = 0.3f * (float)((y / icb) & 1);
        float sby, cby;
        sincosf(w4 * PI * fy * (1.0f / 256.0f), &sby, &cby);
        const int yp = (y & 3) * 32 + (y >> 2);  // permuted for conflict-free LDS
        ytA[yp] = make_float4(Ay, gY, lY, ty);
        ytB[yp] = make_float2(sby, cby);
    }
    __syncthreads();

    const int lane = tid & 31;
    const int wrp  = tid >> 5;
    const float fy0 = (float)(4 * lane);

    float4*       sImg4 = (float4*)s_img;
    const float4* ng4   = (const float4*)(ng + (size_t)b * NPIX);
    const float4* nu4   = (const float4*)(nu + (size_t)b * NPIX);
    const float4* th4   = (const float4*)g_theta;

    float mn = __int_as_float(0x7f800000);
    float mx = __int_as_float(0xff800000);

    #pragma unroll
    for (int g = 0; g < 16; g++) {
        const int q = tid + TPB * g;       // float4-group index
        const int x = wrp + 8 * g;         // warp-uniform row
        const float4 xa = xtA[x];          // broadcast LDS
        const float4 xb = xtB[x];
        const float4 nG = ng4[q];
        const float4 nU = nu4[q];
        const float4 th = th4[q];
        float4 v4;

        #pragma unroll
        for (int j = 0; j < 4; j++) {
            const float4 ya = ytA[j * 32 + lane];
            const float2 yb = ytB[j * 32 + lane];
            const float fy = fy0 + (float)j;
            const float dy = fy - 64.0f;
            const float r  = sqrtf(xa.w + dy * dy);

            // disk
            float v = fminf(fmaxf(w06 - r, 0.0f), 1.0f);
            // central square
            if (xb.z != 0.0f && fy >= sqlo && fy < sqhi) v += 0.5f;
            // axis sinusoids (+ w5 shifted term folded into ya.x)
            v += xa.x + ya.x;
            // diagonal sinusoid via angle addition
            v += xb.x * yb.y + xb.y * yb.x;
            // brightness
            v += w6;
            // gaussian blob (separable)
            v += xa.y * ya.y;
            // ring (predicate-exact: r bit-exact, no fma contraction)
            {
                float t = r - w8_10;
                if (__fmul_rn(t, t) < 10.0f) v += 1.0f;
            }
            // checkerboard: (cpx ^ cpy) * 0.3
            v += (xb.w != 0.0f) ? (0.3f - ya.w) : ya.w;
            // rotated line
            if (fabsf(xa.z + ya.z) < 3.0f) v += 0.6f;
            // angular sinusoid
            {
                const float thv = (j == 0) ? th.x : (j == 1) ? th.y : (j == 2) ? th.z : th.w;
                v += 0.5f * __sinf(thv * m11);
            }
            // noise
            {
                const float gN = (j == 0) ? nG.x : (j == 1) ? nG.y : (j == 2) ? nG.z : nG.w;
                const float uN = (j == 0) ? nU.x : (j == 1) ? nU.y : (j == 2) ? nU.z : nU.w;
                v += gN * c12;
                v += (uN - 0.5f) * c13;
            }
            // contrast + inversion
            v = (v - 0.5f) * c14 + 0.5f;
            if (inv15) v = 1.0f - v;

            mn = fminf(mn, v);
            mx = fmaxf(mx, v);
            if (j == 0) v4.x = v; else if (j == 1) v4.y = v; else if (j == 2) v4.z = v; else v4.w = v;
        }
        sImg4[q] = v4;
    }

    // ---- block min/max reduction ----
    #pragma unroll
    for (int o = 16; o > 0; o >>= 1) {
        mn = fminf(mn, __shfl_xor_sync(0xffffffffu, mn, o));
        mx = fmaxf(mx, __shfl_xor_sync(0xffffffffu, mx, o));
    }
    if (lane == 0) { s_mn[wrp] = mn; s_mx[wrp] = mx; }
    __syncthreads();

    float mnF = s_mn[0], mxF = s_mx[0];
    #pragma unroll
    for (int i = 1; i < 8; i++) {
        mnF = fminf(mnF, s_mn[i]);
        mxF = fmaxf(mxF, s_mx[i]);
    }
    const float invd = 1.0f / (mxF - mnF + 1e-8f);

    // ---- normalize + write ----
    float4* out4 = (float4*)(out + (size_t)b * NPIX);
    #pragma unroll
    for (int g = 0; g < 16; g++) {
        const int q = tid + TPB * g;
        float4 v = sImg4[q];
        v.x = (v.x - mnF) * invd;
        v.y = (v.y - mnF) * invd;
        v.z = (v.z - mnF) * invd;
        v.w = (v.w - mnF) * invd;
        out4[q] = v;
    }
}

extern "C" void kernel_launch(void* const* d_in, const int* in_sizes, int n_in,
                              void* d_out, int out_size) {
    const float* W  = (const float*)d_in[0];
    const float* ng = (const float*)d_in[1];
    const float* nu = (const float*)d_in[2];
    float* out = (float*)d_out;

    cudaFuncSetAttribute(decode_kernel,
                         cudaFuncAttributeMaxDynamicSharedMemorySize, NPIX * 4);

    theta_init_kernel<<<NPIX / TPB, TPB>>>();
    decode_kernel<<<BIMG, TPB, NPIX * 4>>>(W, ng, nu, out);
}

// round 8
// speedup vs baseline: 1.1038x; 1.1038x over previous
#include <cuda_runtime.h>

#define HH    128
#define NPIX  16384
#define TPB   256
#define BIMG  2048

// Weight-independent theta table (atan2(y-cy, x-cx)), rebuilt every launch
// (deterministic), read by all 2048 blocks out of L2.
__device__ float g_theta[NPIX];

__global__ void theta_init_kernel() {
    int p = blockIdx.x * blockDim.x + threadIdx.x;
    if (p < NPIX) {
        float fx = (float)(p >> 7) - 64.0f;   // xx - cx
        float fy = (float)(p & 127) - 64.0f;  // yy - cy
        g_theta[p] = atan2f(fy, fx);          // arctan2(yy-cy, xx-cx)
    }
}

__global__ void __launch_bounds__(TPB, 2) decode_kernel(
    const float* __restrict__ W,
    const float* __restrict__ ng,
    const float* __restrict__ nu,
    float* __restrict__ out)
{
    extern __shared__ float s_img[];  // 16384 floats = 64 KB (dynamic)

    __shared__ float4 xtA[HH];   // {A_x, gX, lX, dx2}
    __shared__ float4 xtB[HH];   // {0.5*sin(ax), 0.5*cos(ax), mXf, cpxf}
    __shared__ float4 ytA[HH];   // natural: {A_y, gY, lY, 0.3*cpy}
    __shared__ float2 ytB[HH];   // natural: {sin(by), cos(by)}
    __shared__ float  s_w[16];
    __shared__ float  s_mn[8], s_mx[8];

    const int tid = threadIdx.x;
    const int b   = blockIdx.x;

    if (tid < 16) s_w[tid] = W[b * 16 + tid];
    __syncthreads();

    const float w0 = s_w[0],  w1 = s_w[1],  w2 = s_w[2],  w3 = s_w[3];
    const float w4 = s_w[4],  w5 = s_w[5],  w6 = s_w[6],  w7 = s_w[7];
    const float w8 = s_w[8],  w9 = s_w[9],  w10 = s_w[10], w11 = s_w[11];
    const float w12 = s_w[12], w13 = s_w[13], w14 = s_w[14], w15 = s_w[15];

    const float PI = 3.14159265358979323846f;

    const float w06   = w0 * 6.0f;
    const float half  = floorf(fminf(fmaxf(fabsf(w1) * 8.0f + 2.0f, 2.0f), 12.0f));
    const float sqlo  = 64.0f - half, sqhi = 64.0f + half;
    const float off   = truncf(w7 * 5.0f);
    const float bxy   = 64.0f + off;
    const float sig   = 4.0f + fabsf(w7) * 5.0f;
    const float ek    = -0.5f / (sig * sig);
    const float w8_10 = w8 * 10.0f;
    const float cb    = floorf(fminf(fmaxf(fabsf(w9) * 8.0f + 2.0f, 2.0f), 16.0f));
    const int   icb   = (int)cb;
    const float angle = w10 * PI;
    const float ca    = cosf(angle);   // accurate: predicate-critical
    const float sa    = sinf(angle);
    const float m11   = w11 * 4.0f;
    const float c12   = 0.2f * w12;
    const float c13   = 0.2f * w13;
    // inversion folded into contrast slope: 1-((v-.5)c+.5) == (v-.5)(-c)+.5 (exact)
    const float c14s  = (w15 > 0.0f) ? -(1.0f + w14) : (1.0f + w14);

    // ---- Build per-x / per-y tables ----
    if (tid < HH) {
        const int i = tid;
        const float fi = (float)i;
        const float di = fi - 64.0f;
        float Ax  = 0.5f * sinf(w2 * 2.0f * PI * fi * (1.0f / 128.0f));
        float gX  = expf(ek * (fi - bxy) * (fi - bxy));
        float lX  = ca * di;
        float dx2 = di * di;
        float sax, cax;
        sincosf(w4 * PI * fi * (1.0f / 256.0f), &sax, &cax);
        float mXf  = (fi >= sqlo && fi < sqhi) ? 1.0f : 0.0f;
        float cpxf = (float)((i / icb) & 1);
        xtA[i] = make_float4(Ax, gX, lX, dx2);
        xtB[i] = make_float4(0.5f * sax, 0.5f * cax, mXf, cpxf);
    } else {
        const int y = tid - HH;
        const float fy = (float)y;
        const float dy = fy - 64.0f;
        float Ay = 0.5f * sinf(w3 * 2.0f * PI * fy * (1.0f / 128.0f))
                 + 0.5f * sinf((fy + w5 * 10.0f) * PI * (1.0f / 128.0f));
        float gY = expf(ek * (fy - bxy) * (fy - bxy));
        float lY = sa * dy;
        float ty = 0.3f * (float)((y / icb) & 1);
        float sby, cby;
        sincosf(w4 * PI * fy * (1.0f / 256.0f), &sby, &cby);
        ytA[y] = make_float4(Ay, gY, lY, ty);
        ytB[y] = make_float2(sby, cby);
    }
    __syncthreads();

    const int lane = tid & 31;
    const int wrp  = tid >> 5;
    const float fy0 = (float)(4 * lane);

    // ---- Hoist y-dependent values into registers (g-invariant) ----
    float addj[4], gYj[4], lYj[4], t2j[4], sbyj[4], cbyj[4], dy2j[4], sqaj[4];
    #pragma unroll
    for (int j = 0; j < 4; j++) {
        const float4 ya = ytA[4 * lane + j];
        const float2 yb = ytB[4 * lane + j];
        const float fy = fy0 + (float)j;
        addj[j] = ya.x + w6 + ya.w;          // Ay + brightness + checker base
        gYj[j]  = ya.y;
        lYj[j]  = ya.z;
        t2j[j]  = 0.3f - 2.0f * ya.w;        // checker flip term (exact)
        sbyj[j] = yb.x;
        cbyj[j] = yb.y;
        const float dy = fy - 64.0f;
        dy2j[j] = dy * dy;
        sqaj[j] = (fy >= sqlo && fy < sqhi) ? 0.5f : 0.0f;
    }

    float4*       sImg4 = (float4*)s_img;
    const float4* ng4   = (const float4*)(ng + (size_t)b * NPIX);
    const float4* nu4   = (const float4*)(nu + (size_t)b * NPIX);
    const float4* th4   = (const float4*)g_theta;

    float mn = __int_as_float(0x7f800000);
    float mx = __int_as_float(0xff800000);

    #pragma unroll
    for (int t = 0; t < 4; t++) {
        // ---- front-batched loads: 12 LDG.128 in flight ----
        float4 bg[4], bu[4], bt[4];
        #pragma unroll
        for (int k = 0; k < 4; k++) {
            const int q = tid + TPB * (4 * t + k);
            bg[k] = ng4[q];
            bu[k] = nu4[q];
            bt[k] = th4[q];
        }
        #pragma unroll
        for (int k = 0; k < 4; k++) {
            const int g = 4 * t + k;
            const int q = tid + TPB * g;
            const int x = wrp + 8 * g;           // warp-uniform row
            const float4 xa = xtA[x];            // broadcast LDS
            const float4 xb = xtB[x];
            float4 v4;

            #pragma unroll
            for (int j = 0; j < 4; j++) {
                const float r = sqrtf(xa.w + dy2j[j]);

                // disk
                float v = fminf(fmaxf(w06 - r, 0.0f), 1.0f);
                // folded additive terms (Ay + w6 + checker base) + x sinusoid
                v += addj[j] + xa.x;
                // central square: mX * {0,0.5}
                v = fmaf(xb.z, sqaj[j], v);
                // diagonal sinusoid via angle addition
                v += xb.x * cbyj[j] + xb.y * sbyj[j];
                // gaussian blob (separable)
                v = fmaf(xa.y, gYj[j], v);
                // ring (predicate-exact)
                {
                    const float tr = r - w8_10;
                    if (__fmul_rn(tr, tr) < 10.0f) v += 1.0f;
                }
                // checkerboard flip: cpx * (0.3 - 2*cpy03)
                v = fmaf(xb.w, t2j[j], v);
                // rotated line
                if (fabsf(xa.z + lYj[j]) < 3.0f) v += 0.6f;
                // angular sinusoid
                {
                    const float thv = (j == 0) ? bt[k].x : (j == 1) ? bt[k].y
                                    : (j == 2) ? bt[k].z : bt[k].w;
                    v = fmaf(0.5f, __sinf(thv * m11), v);
                }
                // noise
                {
                    const float gN = (j == 0) ? bg[k].x : (j == 1) ? bg[k].y
                                   : (j == 2) ? bg[k].z : bg[k].w;
                    const float uN = (j == 0) ? bu[k].x : (j == 1) ? bu[k].y
                                   : (j == 2) ? bu[k].z : bu[k].w;
                    v = fmaf(gN, c12, v);
                    v = fmaf(uN - 0.5f, c13, v);
                }
                // contrast (+inversion folded into c14s)
                v = fmaf(v - 0.5f, c14s, 0.5f);

                mn = fminf(mn, v);
                mx = fmaxf(mx, v);
                if (j == 0) v4.x = v; else if (j == 1) v4.y = v;
                else if (j == 2) v4.z = v; else v4.w = v;
            }
            sImg4[q] = v4;
        }
    }

    // ---- block min/max reduction ----
    #pragma unroll
    for (int o = 16; o > 0; o >>= 1) {
        mn = fminf(mn, __shfl_xor_sync(0xffffffffu, mn, o));
        mx = fmaxf(mx, __shfl_xor_sync(0xffffffffu, mx, o));
    }
    if (lane == 0) { s_mn[wrp] = mn; s_mx[wrp] = mx; }
    __syncthreads();

    float mnF = s_mn[0], mxF = s_mx[0];
    #pragma unroll
    for (int i = 1; i < 8; i++) {
        mnF = fminf(mnF, s_mn[i]);
        mxF = fmaxf(mxF, s_mx[i]);
    }
    const float invd = 1.0f / (mxF - mnF + 1e-8f);

    // ---- normalize + write ----
    float4* out4 = (float4*)(out + (size_t)b * NPIX);
    #pragma unroll
    for (int g = 0; g < 16; g++) {
        const int q = tid + TPB * g;
        float4 v = sImg4[q];
        v.x = (v.x - mnF) * invd;
        v.y = (v.y - mnF) * invd;
        v.z = (v.z - mnF) * invd;
        v.w = (v.w - mnF) * invd;
        out4[q] = v;
    }
}

extern "C" void kernel_launch(void* const* d_in, const int* in_sizes, int n_in,
                              void* d_out, int out_size) {
    const float* W  = (const float*)d_in[0];
    const float* ng = (const float*)d_in[1];
    const float* nu = (const float*)d_in[2];
    float* out = (float*)d_out;

    cudaFuncSetAttribute(decode_kernel,
                         cudaFuncAttributeMaxDynamicSharedMemorySize, NPIX * 4);

    theta_init_kernel<<<128, 128>>>();
    decode_kernel<<<BIMG, TPB, NPIX * 4>>>(W, ng, nu, out);
}

// round 12
// speedup vs baseline: 1.1282x; 1.0221x over previous
#include <cuda_runtime.h>

#define HH    128
#define NPIX  16384
#define TPB   256
#define BIMG  2048

// Weight-independent theta table (atan2(y-cy, x-cx)), rebuilt every launch
// (deterministic), read by all 2048 blocks out of L2.
__device__ float g_theta[NPIX];

__global__ void theta_init_kernel() {
    int p = blockIdx.x * blockDim.x + threadIdx.x;
    if (p < NPIX) {
        float fx = (float)(p >> 7) - 64.0f;   // xx - cx
        float fy = (float)(p & 127) - 64.0f;  // yy - cy
        g_theta[p] = atan2f(fy, fx);          // arctan2(yy-cy, xx-cx)
    }
}

__global__ void __launch_bounds__(TPB, 2) decode_kernel(
    const float* __restrict__ W,
    const float* __restrict__ ng,
    const float* __restrict__ nu,
    float* __restrict__ out)
{
    extern __shared__ float s_img[];  // 16384 floats = 64 KB (dynamic)

    __shared__ float4 xtA[HH];   // {A_x, gX, lX, dx2}
    __shared__ float4 xtB[HH];   // {0.5*sin(ax), 0.5*cos(ax), mXf, cpxf}
    __shared__ float4 ytA[HH];   // {A_y, gY, lY, 0.3*cpy}
    __shared__ float2 ytB[HH];   // {sin(by), cos(by)}
    __shared__ float  s_w[16];
    __shared__ float  s_mn[8], s_mx[8];

    const int tid = threadIdx.x;
    const int b   = blockIdx.x;

    if (tid < 16) s_w[tid] = W[b * 16 + tid];
    __syncthreads();

    const float w0 = s_w[0],  w1 = s_w[1],  w2 = s_w[2],  w3 = s_w[3];
    const float w4 = s_w[4],  w5 = s_w[5],  w6 = s_w[6],  w7 = s_w[7];
    const float w8 = s_w[8],  w9 = s_w[9],  w10 = s_w[10], w11 = s_w[11];
    const float w12 = s_w[12], w13 = s_w[13], w14 = s_w[14], w15 = s_w[15];

    const float PI = 3.14159265358979323846f;

    const float w06   = w0 * 6.0f;
    const float half  = floorf(fminf(fmaxf(fabsf(w1) * 8.0f + 2.0f, 2.0f), 12.0f));
    const float sqlo  = 64.0f - half, sqhi = 64.0f + half;
    const float off   = truncf(w7 * 5.0f);
    const float bxy   = 64.0f + off;
    const float sig   = 4.0f + fabsf(w7) * 5.0f;
    const float ek    = -0.5f / (sig * sig);
    const float w8_10 = w8 * 10.0f;
    const float cb    = floorf(fminf(fmaxf(fabsf(w9) * 8.0f + 2.0f, 2.0f), 16.0f));
    const int   icb   = (int)cb;
    const float angle = w10 * PI;
    const float ca    = cosf(angle);   // accurate: predicate-critical
    const float sa    = sinf(angle);
    const float m11   = w11 * 4.0f;
    const float c12   = 0.2f * w12;
    const float c13   = 0.2f * w13;
    // inversion folded into contrast slope: 1-((v-.5)c+.5) == (v-.5)(-c)+.5 (exact)
    const float c14s  = (w15 > 0.0f) ? -(1.0f + w14) : (1.0f + w14);

    // ---- Build per-x / per-y tables ----
    if (tid < HH) {
        const int i = tid;
        const float fi = (float)i;
        const float di = fi - 64.0f;
        float Ax  = 0.5f * sinf(w2 * 2.0f * PI * fi * (1.0f / 128.0f));
        float gX  = expf(ek * (fi - bxy) * (fi - bxy));
        float lX  = ca * di;
        float dx2 = di * di;
        float sax, cax;
        sincosf(w4 * PI * fi * (1.0f / 256.0f), &sax, &cax);
        float mXf  = (fi >= sqlo && fi < sqhi) ? 1.0f : 0.0f;
        float cpxf = (float)((i / icb) & 1);
        xtA[i] = make_float4(Ax, gX, lX, dx2);
        xtB[i] = make_float4(0.5f * sax, 0.5f * cax, mXf, cpxf);
    } else {
        const int y = tid - HH;
        const float fy = (float)y;
        const float dy = fy - 64.0f;
        float Ay = 0.5f * sinf(w3 * 2.0f * PI * fy * (1.0f / 128.0f))
                 + 0.5f * sinf((fy + w5 * 10.0f) * PI * (1.0f / 128.0f));
        float gY = expf(ek * (fy - bxy) * (fy - bxy));
        float lY = sa * dy;
        float ty = 0.3f * (float)((y / icb) & 1);
        float sby, cby;
        sincosf(w4 * PI * fy * (1.0f / 256.0f), &sby, &cby);
        ytA[y] = make_float4(Ay, gY, lY, ty);
        ytB[y] = make_float2(sby, cby);
    }
    __syncthreads();

    const int lane = tid & 31;
    const int wrp  = tid >> 5;
    const float fy0 = (float)(4 * lane);

    // ---- Hoist y-dependent values into registers (g-invariant) ----
    float addj[4], gYj[4], lYj[4], t2j[4], sbyj[4], cbyj[4], dy2j[4], sqaj[4];
    #pragma unroll
    for (int j = 0; j < 4; j++) {
        const float4 ya = ytA[4 * lane + j];
        const float2 yb = ytB[4 * lane + j];
        const float fy = fy0 + (float)j;
        addj[j] = ya.x + w6 + ya.w;          // Ay + brightness + checker base
        gYj[j]  = ya.y;
        lYj[j]  = ya.z;
        t2j[j]  = 0.3f - 2.0f * ya.w;        // checker flip term (exact)
        sbyj[j] = yb.x;
        cbyj[j] = yb.y;
        const float dy = fy - 64.0f;
        dy2j[j] = dy * dy;
        sqaj[j] = (fy >= sqlo && fy < sqhi) ? 0.5f : 0.0f;
    }

    float4*       sImg4 = (float4*)s_img;
    const float4* ng4   = (const float4*)(ng + (size_t)b * NPIX);
    const float4* nu4   = (const float4*)(nu + (size_t)b * NPIX);
    const float4* th4   = (const float4*)g_theta;

    float mn = __int_as_float(0x7f800000);
    float mx = __int_as_float(0xff800000);

    // ---- software-pipelined mainloop: 8 stages x 2 groups, depth-1 prefetch ----
    float4 bg[2][2], bu[2][2], bt[2][2];

    // prologue: stage 0 loads
    #pragma unroll
    for (int k = 0; k < 2; k++) {
        const int q = tid + TPB * k;
        bg[0][k] = ng4[q];
        bu[0][k] = nu4[q];
        bt[0][k] = th4[q];
    }

    #pragma unroll
    for (int t = 0; t < 8; t++) {
        const int cur = t & 1, nxt = cur ^ 1;
        // prefetch stage t+1 while stage t computes
        if (t < 7) {
            #pragma unroll
            for (int k = 0; k < 2; k++) {
                const int q = tid + TPB * (2 * (t + 1) + k);
                bg[nxt][k] = ng4[q];
                bu[nxt][k] = nu4[q];
                bt[nxt][k] = th4[q];
            }
        }
        #pragma unroll
        for (int k = 0; k < 2; k++) {
            const int g = 2 * t + k;
            const int q = tid + TPB * g;
            const int x = wrp + 8 * g;           // warp-uniform row
            const float4 xa = xtA[x];            // broadcast LDS
            const float4 xb = xtB[x];
            float4 v4;

            #pragma unroll
            for (int j = 0; j < 4; j++) {
                const float r = sqrtf(xa.w + dy2j[j]);

                // disk
                float v = fminf(fmaxf(w06 - r, 0.0f), 1.0f);
                // folded additive terms (Ay + w6 + checker base) + x sinusoid
                v += addj[j] + xa.x;
                // central square: mX * {0,0.5}
                v = fmaf(xb.z, sqaj[j], v);
                // diagonal sinusoid via angle addition
                v += xb.x * cbyj[j] + xb.y * sbyj[j];
                // gaussian blob (separable)
                v = fmaf(xa.y, gYj[j], v);
                // ring (predicate-exact)
                {
                    const float tr = r - w8_10;
                    if (__fmul_rn(tr, tr) < 10.0f) v += 1.0f;
                }
                // checkerboard flip: cpx * (0.3 - 2*cpy03)
                v = fmaf(xb.w, t2j[j], v);
                // rotated line
                if (fabsf(xa.z + lYj[j]) < 3.0f) v += 0.6f;
                // angular sinusoid
                {
                    const float thv = (j == 0) ? bt[cur][k].x : (j == 1) ? bt[cur][k].y
                                    : (j == 2) ? bt[cur][k].z : bt[cur][k].w;
                    v = fmaf(0.5f, __sinf(thv * m11), v);
                }
                // noise
                {
                    const float gN = (j == 0) ? bg[cur][k].x : (j == 1) ? bg[cur][k].y
                                   : (j == 2) ? bg[cur][k].z : bg[cur][k].w;
                    const float uN = (j == 0) ? bu[cur][k].x : (j == 1) ? bu[cur][k].y
                                   : (j == 2) ? bu[cur][k].z : bu[cur][k].w;
                    v = fmaf(gN, c12, v);
                    v = fmaf(uN - 0.5f, c13, v);
                }
                // contrast (+inversion folded into c14s)
                v = fmaf(v - 0.5f, c14s, 0.5f);

                mn = fminf(mn, v);
                mx = fmaxf(mx, v);
                if (j == 0) v4.x = v; else if (j == 1) v4.y = v;
                else if (j == 2) v4.z = v; else v4.w = v;
            }
            sImg4[q] = v4;
        }
    }

    // ---- block min/max reduction ----
    #pragma unroll
    for (int o = 16; o > 0; o >>= 1) {
        mn = fminf(mn, __shfl_xor_sync(0xffffffffu, mn, o));
        mx = fmaxf(mx, __shfl_xor_sync(0xffffffffu, mx, o));
    }
    if (lane == 0) { s_mn[wrp] = mn; s_mx[wrp] = mx; }
    __syncthreads();

    float mnF = s_mn[0], mxF = s_mx[0];
    #pragma unroll
    for (int i = 1; i < 8; i++) {
        mnF = fminf(mnF, s_mn[i]);
        mxF = fmaxf(mxF, s_mx[i]);
    }
    const float invd = 1.0f / (mxF - mnF + 1e-8f);

    // ---- normalize + write ----
    float4* out4 = (float4*)(out + (size_t)b * NPIX);
    #pragma unroll
    for (int g = 0; g < 16; g++) {
        const int q = tid + TPB * g;
        float4 v = sImg4[q];
        v.x = (v.x - mnF) * invd;
        v.y = (v.y - mnF) * invd;
        v.z = (v.z - mnF) * invd;
        v.w = (v.w - mnF) * invd;
        out4[q] = v;
    }
}

extern "C" void kernel_launch(void* const* d_in, const int* in_sizes, int n_in,
                              void* d_out, int out_size) {
    const float* W  = (const float*)d_in[0];
    const float* ng = (const float*)d_in[1];
    const float* nu = (const float*)d_in[2];
    float* out = (float*)d_out;

    cudaFuncSetAttribute(decode_kernel,
                         cudaFuncAttributeMaxDynamicSharedMemorySize, NPIX * 4);

    theta_init_kernel<<<128, 128>>>();
    decode_kernel<<<BIMG, TPB, NPIX * 4>>>(W, ng, nu, out);
}